// round 11
// baseline (speedup 1.0000x reference)
#include <cuda_runtime.h>
#include <cstdint>

// Problem constants
#define C_DIM   384
#define N_DIM   1152
#define B_SZ    8
#define H_IMG   224
#define W_IMG   224
#define HWB     50176
#define M_TOT   401408
#define HD      96
#define NHEADS  4

// QKV scratch in fp16 (half2 words): [M_TOT][576 words]; q pre-scaled by 96^-0.5
__device__ uint32_t g_qkvh[(size_t)M_TOT * 576];
// Pre-converted W in fp16 (half2 words): [1152][384] halves
__device__ uint32_t g_wh[221184];

__device__ __forceinline__ uint32_t pack_h2(float lo, float hi) {
    uint32_t r;
    asm("cvt.rn.f16x2.f32 %0, %1, %2;" : "=r"(r) : "f"(hi), "f"(lo));
    return r;   // d<15:0> = lo, d<31:16> = hi
}

__device__ __forceinline__ uint32_t smem_u32(const void* p) {
    uint32_t a;
    asm("{ .reg .u64 t; cvta.to.shared.u64 t, %1; cvt.u32.u64 %0, t; }"
        : "=r"(a) : "l"(p));
    return a;
}

#define CP_ASYNC16(dst, src) \
    asm volatile("cp.async.cg.shared.global [%0], [%1], 16;" \
                 :: "r"(dst), "l"(src) : "memory")
#define CP_COMMIT()  asm volatile("cp.async.commit_group;" ::: "memory")
#define CP_WAIT0()   asm volatile("cp.async.wait_group 0;" ::: "memory")

__device__ __forceinline__ void ldsm_x4(uint32_t& r0, uint32_t& r1,
                                        uint32_t& r2, uint32_t& r3, uint32_t a) {
    asm volatile("ldmatrix.sync.aligned.m8n8.x4.shared.b16 {%0,%1,%2,%3}, [%4];"
                 : "=r"(r0), "=r"(r1), "=r"(r2), "=r"(r3) : "r"(a));
}
__device__ __forceinline__ void ldsm_x4_t(uint32_t& r0, uint32_t& r1,
                                          uint32_t& r2, uint32_t& r3, uint32_t a) {
    asm volatile("ldmatrix.sync.aligned.m8n8.x4.trans.shared.b16 {%0,%1,%2,%3}, [%4];"
                 : "=r"(r0), "=r"(r1), "=r"(r2), "=r"(r3) : "r"(a));
}

__device__ __forceinline__ void mma_f16(float& c0, float& c1, float& c2, float& c3,
                                        uint32_t a0, uint32_t a1, uint32_t a2, uint32_t a3,
                                        uint32_t b0, uint32_t b1) {
    asm volatile(
        "mma.sync.aligned.m16n8k16.row.col.f32.f16.f16.f32 "
        "{%0,%1,%2,%3}, {%4,%5,%6,%7}, {%8,%9}, {%0,%1,%2,%3};"
        : "+f"(c0), "+f"(c1), "+f"(c2), "+f"(c3)
        : "r"(a0), "r"(a1), "r"(a2), "r"(a3), "r"(b0), "r"(b1));
}

// ---------------------------------------------------------------------------
// Kernel 0: one-time W fp32 -> fp16 conversion
// ---------------------------------------------------------------------------
__global__ void __launch_bounds__(256) wconv(const float* __restrict__ w)
{
    int i = blockIdx.x * 256 + threadIdx.x;
    if (i < 110592) {
        float4 v = ((const float4*)w)[i];
        uint2 o;
        o.x = pack_h2(v.x, v.y);
        o.y = pack_h2(v.z, v.w);
        ((uint2*)g_wh)[i] = o;
    }
}

// ---------------------------------------------------------------------------
// Kernel 1: QKV GEMM — double-buffered cp.async pipeline.
//   A[k][m] fp16, 256B rows, XOR swizzle: phys_chunk = (c&8)|((c&7)^(k&7)).
//   B stages: 16 k x 128 n, stride 24 halves (48B) -> conflict-free ldsm.
//   24 stages per N-tile, prefetch s+1 before computing s, 1 sync/stage.
// ---------------------------------------------------------------------------
#define AS_BYTES 98304                      // 384 * 256
#define BSTG     6144                       // 128 rows * 48B
#define QKV_SMEM (AS_BYTES + 2 * BSTG)      // 110,592 -> 2 CTAs/SM

__global__ void __launch_bounds__(256, 2) qkv_mma(
    const float* __restrict__ x,
    const float* __restrict__ bias)
{
    extern __shared__ char smem[];
    const uint32_t abase = smem_u32(smem);
    const uint32_t bbase = abase + AS_BYTES;

    const int tid = threadIdx.x;
    const int wid = tid >> 5;
    const int lid = tid & 31;
    const int mw  = wid & 1;
    const int nw  = wid >> 1;
    const int lq  = lid >> 2;
    const int lr  = lid & 3;
    const int bit3 = (lid >> 3) & 1;
    const int bit4 = (lid >> 4) & 1;

    const int m0 = blockIdx.x * 128;
    const int b  = m0 / HWB;
    const float* xb = x + (size_t)b * C_DIM * HWB + (m0 - b * HWB);

    // B-stage cp.async mapping: thread -> (row = tid>>1, 16B chunk = tid&1)
    const int bs_row = tid >> 1;
    const int bs_c   = tid & 1;
    const uint32_t bs_dsto = (uint32_t)(bs_row * 48 + bs_c * 16);
    const uint32_t* bs_srco = g_wh + (size_t)bs_row * 192 + bs_c * 4;

    // ---- Preload stage (nt=0, s=0) into buf 0, then A prologue ----
    CP_ASYNC16(bbase + bs_dsto, (const void*)bs_srco);
    CP_COMMIT();

    // A prologue: As[k][m] fp16, XOR-swizzled chunks
    for (int i = tid; i < 12288; i += 256) {
        int k = i >> 5, m4 = i & 31;
        float4 v = *(const float4*)(xb + (size_t)k * HWB + m4 * 4);
        uint32_t h0 = pack_h2(v.x, v.y);
        uint32_t h1 = pack_h2(v.z, v.w);
        int cl = m4 >> 1;
        uint32_t off = (uint32_t)(k * 256
            + (((cl & 8) | ((cl & 7) ^ (k & 7))) * 16) + (m4 & 1) * 8);
        asm volatile("st.shared.v2.b32 [%0], {%1,%2};"
                     :: "r"(abase + off), "r"(h0), "r"(h1));
    }
    CP_WAIT0();
    __syncthreads();

    // Per-lane ldmatrix address components
    // A (.trans): row = (lid&7) + bit4*8 within stage; swizzled column offsets
    const uint32_t a_row = (uint32_t)((((lid & 7) + bit4 * 8) * 256) + mw * 128);
    uint32_t coff[4];
    #pragma unroll
    for (int i = 0; i < 4; ++i)
        coff[i] = (uint32_t)((((bit3 + 2 * i) ^ (lid & 7)) & 7) * 16);
    // B (non-trans): row = n, 16B chunk = bit3 (k halves 0-7 / 8-15)
    const uint32_t b_lane = (uint32_t)((nw * 32 + bit4 * 8 + (lid & 7)) * 48
                                       + bit3 * 16);

    for (int nt = 0; nt < 9; ++nt) {
        const int n0 = nt * 128;
        float c[4][4][4];
        #pragma unroll
        for (int i = 0; i < 4; ++i)
            #pragma unroll
            for (int j = 0; j < 4; ++j)
                c[i][j][0] = c[i][j][1] = c[i][j][2] = c[i][j][3] = 0.f;

        for (int s = 0; s < 24; ++s) {
            // ---- Prefetch stage s+1 (or next tile's stage 0) ----
            const bool pf = (s < 23) || (nt < 8);
            if (pf) {
                const int pn0 = (s < 23) ? n0 : n0 + 128;
                const int ps  = (s < 23) ? s + 1 : 0;
                CP_ASYNC16(bbase + (uint32_t)(((s + 1) & 1) * BSTG) + bs_dsto,
                           (const void*)(bs_srco + (size_t)pn0 * 192 + ps * 8));
                CP_COMMIT();
            }

            // ---- Compute stage s from buf (s & 1) ----
            const uint32_t sA = abase + (uint32_t)(s * 4096) + a_row;
            const uint32_t sB = bbase + (uint32_t)((s & 1) * BSTG) + b_lane;
            uint32_t a[4][4], bb[2][4];
            #pragma unroll
            for (int i = 0; i < 4; ++i)
                ldsm_x4_t(a[i][0], a[i][1], a[i][2], a[i][3], sA + coff[i]);
            #pragma unroll
            for (int jp = 0; jp < 2; ++jp)
                ldsm_x4(bb[jp][0], bb[jp][1], bb[jp][2], bb[jp][3],
                        sB + (uint32_t)(jp * 16 * 48));
            #pragma unroll
            for (int i = 0; i < 4; ++i)
                #pragma unroll
                for (int j = 0; j < 4; ++j) {
                    const int jp = j >> 1, lo = (j & 1) * 2;
                    mma_f16(c[i][j][0], c[i][j][1], c[i][j][2], c[i][j][3],
                            a[i][0], a[i][1], a[i][2], a[i][3],
                            bb[jp][lo], bb[jp][lo + 1]);
                }

            if (pf) CP_WAIT0();
            __syncthreads();
        }

        // ---- Epilogue: bias + q-scale, pack fp16, quad transpose, STG.128 ----
        const float qsc = (n0 < 384) ? 0.10206207261596577f : 1.0f;
        float2 bv[4];
        #pragma unroll
        for (int j = 0; j < 4; ++j)
            bv[j] = *(const float2*)(bias + n0 + nw * 32 + j * 8 + lr * 2);

        const int gcol = (n0 + nw * 32 + lr * 8) >> 1;
        #pragma unroll
        for (int i = 0; i < 4; ++i) {
            uint32_t v0[4], v1[4];
            #pragma unroll
            for (int j = 0; j < 4; ++j) {
                v0[j] = pack_h2((c[i][j][0] + bv[j].x) * qsc,
                                (c[i][j][1] + bv[j].y) * qsc);
                v1[j] = pack_h2((c[i][j][2] + bv[j].x) * qsc,
                                (c[i][j][3] + bv[j].y) * qsc);
            }
            #pragma unroll
            for (int m = 1; m < 4; ++m) {
                v0[lr ^ m] = __shfl_xor_sync(0xffffffffu, v0[lr ^ m], m);
                v1[lr ^ m] = __shfl_xor_sync(0xffffffffu, v1[lr ^ m], m);
            }
            const int gm0 = m0 + mw * 64 + i * 16 + lq;
            *(uint4*)(g_qkvh + (size_t)gm0 * 576 + gcol) =
                make_uint4(v0[0], v0[1], v0[2], v0[3]);
            *(uint4*)(g_qkvh + (size_t)(gm0 + 8) * 576 + gcol) =
                make_uint4(v1[0], v1[1], v1[2], v1[3]);
        }
    }
}

// ---------------------------------------------------------------------------
// Kernel 2: tensor-core windowed attention (cp.async prologue; unchanged R10)
// ---------------------------------------------------------------------------
#define ROWB 208                      // bytes per Q/K/V row (104 halves)
#define MATB (64 * ROWB)              // 13312 bytes per matrix
#define AT_SMEM (3 * MATB)            // 39936

__global__ void __launch_bounds__(128) attn_tc(float* __restrict__ out)
{
    extern __shared__ char smem[];
    const uint32_t qb = smem_u32(smem);
    const uint32_t kb = qb + MATB;
    const uint32_t vb = kb + MATB;
    uint32_t* smw = (uint32_t*)smem;
    float* osm = (float*)smem;        // reused AFTER AV (post-sync)

    const int tid  = threadIdx.x;
    const int wrp  = tid >> 5;
    const int lid  = tid & 31;
    const int lam  = lid & 3;
    const int win  = blockIdx.x;
    const int head = blockIdx.y;
    const int b    = win >> 10;
    const int wh   = (win >> 5) & 31;
    const int ww   = win & 31;

    // Kick off all Q/K/V loads first: fire-and-forget cp.async (16B each)
    #pragma unroll
    for (int p = 0; p < 14; ++p) {
        int e = p * 128 + tid;
        if (e < 1764) {
            int tok = e / 36, r = e % 36;
            int seg = r / 12, f4 = r % 12;
            const uint32_t* src = g_qkvh
                + ((size_t)b * HWB + (wh * 7 + tok / 7) * W_IMG + ww * 7 + tok % 7) * 576
                + seg * 192 + head * 48 + f4 * 4;
            uint32_t dst = qb + (uint32_t)(seg * MATB + tok * ROWB + f4 * 16);
            CP_ASYNC16(dst, (const void*)src);
        }
    }
    CP_COMMIT();

    // Zero pad rows 49..63 of Q/K/V while loads fly (52 words per row)
    for (int i = tid; i < 2340; i += 128) {
        int arr = i / 780, rem = i % 780;
        smw[arr * 3328 + (49 + rem / 52) * 52 + (rem % 52)] = 0u;
    }
    CP_WAIT0();
    __syncthreads();

    // ---- Scores: S[q][key] = Q . K ----
    const int q0 = wrp * 16;
    const uint32_t a_addr = qb + (uint32_t)((q0 + (lid & 15)) * ROWB + (lid >> 4) * 16);
    const uint32_t k_rsel = (uint32_t)((((lid >> 4) & 1) * 8 + (lid & 7)) * ROWB
                                       + ((lid >> 3) & 1) * 16);
    float sc[7][4];
    #pragma unroll
    for (int t = 0; t < 7; ++t)
        sc[t][0] = sc[t][1] = sc[t][2] = sc[t][3] = 0.f;

    #pragma unroll
    for (int s = 0; s < 6; ++s) {
        uint32_t a0, a1, a2, a3;
        ldsm_x4(a0, a1, a2, a3, a_addr + (uint32_t)(s * 32));
        #pragma unroll
        for (int np = 0; np < 4; ++np) {
            uint32_t r0, r1, r2, r3;
            ldsm_x4(r0, r1, r2, r3, kb + k_rsel + (uint32_t)(np * 16 * ROWB + s * 32));
            mma_f16(sc[2*np][0], sc[2*np][1], sc[2*np][2], sc[2*np][3],
                    a0, a1, a2, a3, r0, r1);
            if (np < 3)
                mma_f16(sc[2*np+1][0], sc[2*np+1][1], sc[2*np+1][2], sc[2*np+1][3],
                        a0, a1, a2, a3, r2, r3);
        }
    }

    // ---- Softmax in registers ----
    float mx0 = -1e30f, mx1 = -1e30f;
    #pragma unroll
    for (int t = 0; t < 6; ++t) {
        mx0 = fmaxf(mx0, fmaxf(sc[t][0], sc[t][1]));
        mx1 = fmaxf(mx1, fmaxf(sc[t][2], sc[t][3]));
    }
    if (lam == 0) { mx0 = fmaxf(mx0, sc[6][0]); mx1 = fmaxf(mx1, sc[6][2]); }
    mx0 = fmaxf(mx0, __shfl_xor_sync(0xffffffffu, mx0, 1));
    mx0 = fmaxf(mx0, __shfl_xor_sync(0xffffffffu, mx0, 2));
    mx1 = fmaxf(mx1, __shfl_xor_sync(0xffffffffu, mx1, 1));
    mx1 = fmaxf(mx1, __shfl_xor_sync(0xffffffffu, mx1, 2));

    float pr[7][4];
    float sum0 = 0.f, sum1 = 0.f;
    #pragma unroll
    for (int t = 0; t < 6; ++t) {
        pr[t][0] = __expf(sc[t][0] - mx0);
        pr[t][1] = __expf(sc[t][1] - mx0);
        pr[t][2] = __expf(sc[t][2] - mx1);
        pr[t][3] = __expf(sc[t][3] - mx1);
        sum0 += pr[t][0] + pr[t][1];
        sum1 += pr[t][2] + pr[t][3];
    }
    pr[6][0] = (lam == 0) ? __expf(sc[6][0] - mx0) : 0.f;
    pr[6][1] = 0.f;
    pr[6][2] = (lam == 0) ? __expf(sc[6][2] - mx1) : 0.f;
    pr[6][3] = 0.f;
    sum0 += pr[6][0];
    sum1 += pr[6][2];
    sum0 += __shfl_xor_sync(0xffffffffu, sum0, 1);
    sum0 += __shfl_xor_sync(0xffffffffu, sum0, 2);
    sum1 += __shfl_xor_sync(0xffffffffu, sum1, 1);
    sum1 += __shfl_xor_sync(0xffffffffu, sum1, 2);
    const float inv0 = 1.f / sum0;
    const float inv1 = 1.f / sum1;

    // ---- AV: out = P . V ----
    float co[12][4];
    #pragma unroll
    for (int t = 0; t < 12; ++t)
        co[t][0] = co[t][1] = co[t][2] = co[t][3] = 0.f;

    const uint32_t v_rsel = (uint32_t)((lid & 15) * ROWB + ((lid >> 4) & 1) * 16);
    #pragma unroll
    for (int t = 0; t < 4; ++t) {
        uint32_t a0 = pack_h2(pr[2*t][0], pr[2*t][1]);
        uint32_t a1 = pack_h2(pr[2*t][2], pr[2*t][3]);
        uint32_t a2 = 0u, a3 = 0u;
        if (t < 3) {
            a2 = pack_h2(pr[2*t+1][0], pr[2*t+1][1]);
            a3 = pack_h2(pr[2*t+1][2], pr[2*t+1][3]);
        }
        #pragma unroll
        for (int np = 0; np < 6; ++np) {
            uint32_t r0, r1, r2, r3;
            ldsm_x4_t(r0, r1, r2, r3, vb + v_rsel + (uint32_t)(t * 16 * ROWB + np * 32));
            mma_f16(co[2*np][0], co[2*np][1], co[2*np][2], co[2*np][3],
                    a0, a1, a2, a3, r0, r1);
            mma_f16(co[2*np+1][0], co[2*np+1][1], co[2*np+1][2], co[2*np+1][3],
                    a0, a1, a2, a3, r2, r3);
        }
    }
    __syncthreads();

    // ---- Stage normalized output rows to osm[49][96] ----
    {
        const int r   = lid >> 2;
        const int rg0 = q0 + r;
        const int rg8 = q0 + r + 8;
        #pragma unroll
        for (int nt = 0; nt < 12; ++nt) {
            const int d = nt * 8 + 2 * lam;
            if (rg0 < 49)
                *(float2*)(osm + rg0 * 96 + d) =
                    make_float2(co[nt][0] * inv0, co[nt][1] * inv0);
            if (rg8 < 49)
                *(float2*)(osm + rg8 * 96 + d) =
                    make_float2(co[nt][2] * inv1, co[nt][3] * inv1);
        }
    }
    __syncthreads();

    // ---- Coalesced-ish global write (w-contiguous runs of 7) ----
    for (int e = tid; e < 4704; e += 128) {
        int tok = e % 49, d = e / 49;
        out[(((size_t)b * C_DIM + head * HD + d) * H_IMG + wh * 7 + tok / 7) * W_IMG
            + ww * 7 + tok % 7] = osm[tok * 96 + d];
    }
}

// ---------------------------------------------------------------------------
extern "C" void kernel_launch(void* const* d_in, const int* in_sizes, int n_in,
                              void* d_out, int out_size)
{
    const float* x    = (const float*)d_in[0];
    const float* w    = (const float*)d_in[1];
    const float* bias = (const float*)d_in[2];
    float* out        = (float*)d_out;

    cudaFuncSetAttribute(qkv_mma, cudaFuncAttributeMaxDynamicSharedMemorySize,
                         (int)QKV_SMEM);
    cudaFuncSetAttribute(attn_tc, cudaFuncAttributeMaxDynamicSharedMemorySize,
                         (int)AT_SMEM);

    wconv<<<432, 256>>>(w);
    qkv_mma<<<M_TOT / 128, 256, QKV_SMEM>>>(x, bias);
    attn_tc<<<dim3(B_SZ * 32 * 32, NHEADS), 128, AT_SMEM>>>(out);
}

// round 12
// speedup vs baseline: 1.1792x; 1.1792x over previous
#include <cuda_runtime.h>
#include <cstdint>

// Problem constants
#define C_DIM   384
#define N_DIM   1152
#define B_SZ    8
#define H_IMG   224
#define W_IMG   224
#define HWB     50176
#define M_TOT   401408
#define HD      96
#define NHEADS  4

// QKV scratch in fp16 (half2 words): [M_TOT][576 words]; q pre-scaled by 96^-0.5
__device__ uint32_t g_qkvh[(size_t)M_TOT * 576];
// Pre-converted W in fp16 (half2 words): [1152][384] halves
__device__ uint32_t g_wh[221184];

__device__ __forceinline__ uint32_t pack_h2(float lo, float hi) {
    uint32_t r;
    asm("cvt.rn.f16x2.f32 %0, %1, %2;" : "=r"(r) : "f"(hi), "f"(lo));
    return r;   // d<15:0> = lo, d<31:16> = hi
}

__device__ __forceinline__ uint32_t smem_u32(const void* p) {
    uint32_t a;
    asm("{ .reg .u64 t; cvta.to.shared.u64 t, %1; cvt.u32.u64 %0, t; }"
        : "=r"(a) : "l"(p));
    return a;
}

#define CP_ASYNC16(dst, src) \
    asm volatile("cp.async.cg.shared.global [%0], [%1], 16;" \
                 :: "r"(dst), "l"(src) : "memory")
#define CP_COMMIT()  asm volatile("cp.async.commit_group;" ::: "memory")
#define CP_WAIT0()   asm volatile("cp.async.wait_group 0;" ::: "memory")

__device__ __forceinline__ void ldsm_x4(uint32_t& r0, uint32_t& r1,
                                        uint32_t& r2, uint32_t& r3, uint32_t a) {
    asm volatile("ldmatrix.sync.aligned.m8n8.x4.shared.b16 {%0,%1,%2,%3}, [%4];"
                 : "=r"(r0), "=r"(r1), "=r"(r2), "=r"(r3) : "r"(a));
}
__device__ __forceinline__ void ldsm_x4_t(uint32_t& r0, uint32_t& r1,
                                          uint32_t& r2, uint32_t& r3, uint32_t a) {
    asm volatile("ldmatrix.sync.aligned.m8n8.x4.trans.shared.b16 {%0,%1,%2,%3}, [%4];"
                 : "=r"(r0), "=r"(r1), "=r"(r2), "=r"(r3) : "r"(a));
}

__device__ __forceinline__ void mma_f16(float& c0, float& c1, float& c2, float& c3,
                                        uint32_t a0, uint32_t a1, uint32_t a2, uint32_t a3,
                                        uint32_t b0, uint32_t b1) {
    asm volatile(
        "mma.sync.aligned.m16n8k16.row.col.f32.f16.f16.f32 "
        "{%0,%1,%2,%3}, {%4,%5,%6,%7}, {%8,%9}, {%0,%1,%2,%3};"
        : "+f"(c0), "+f"(c1), "+f"(c2), "+f"(c3)
        : "r"(a0), "r"(a1), "r"(a2), "r"(a3), "r"(b0), "r"(b1));
}

// ---------------------------------------------------------------------------
// Kernel 0: one-time W fp32 -> fp16 conversion
// ---------------------------------------------------------------------------
__global__ void __launch_bounds__(256) wconv(const float* __restrict__ w)
{
    int i = blockIdx.x * 256 + threadIdx.x;
    if (i < 110592) {
        float4 v = ((const float4*)w)[i];
        uint2 o;
        o.x = pack_h2(v.x, v.y);
        o.y = pack_h2(v.z, v.w);
        ((uint2*)g_wh)[i] = o;
    }
}

// ---------------------------------------------------------------------------
// Kernel 1: QKV GEMM (exact Round-10 structure; B stages via in-stage cp.async)
// ---------------------------------------------------------------------------
#define ASTH 136
#define BSTH 40
#define AS_BYTES (384 * ASTH * 2)
#define QKV_SMEM (AS_BYTES + 128 * BSTH * 2)

__global__ void __launch_bounds__(256, 2) qkv_mma(
    const float* __restrict__ x,
    const float* __restrict__ bias)
{
    extern __shared__ char smem[];
    const uint32_t abase = smem_u32(smem);
    const uint32_t bbase = abase + AS_BYTES;

    const int tid = threadIdx.x;
    const int wid = tid >> 5;
    const int lid = tid & 31;
    const int mw  = wid & 1;
    const int nw  = wid >> 1;
    const int lq  = lid >> 2;
    const int lr  = lid & 3;

    const int m0 = blockIdx.x * 128;
    const int b  = m0 / HWB;
    const float* xb = x + (size_t)b * C_DIM * HWB + (m0 - b * HWB);

    for (int i = tid; i < 12288; i += 256) {
        int k = i >> 5, m4 = i & 31;
        float4 v = *(const float4*)(xb + (size_t)k * HWB + m4 * 4);
        uint32_t h0 = pack_h2(v.x, v.y);
        uint32_t h1 = pack_h2(v.z, v.w);
        uint32_t dst = abase + (uint32_t)(k * ASTH + m4 * 4) * 2;
        asm volatile("st.shared.v2.b32 [%0], {%1,%2};" :: "r"(dst), "r"(h0), "r"(h1));
    }

    const uint32_t a_lane = (uint32_t)(((lid & 7) + ((lid >> 4) & 1) * 8) * (ASTH * 2)
                                       + (mw * 64 + ((lid >> 3) & 1) * 8) * 2);
    const uint32_t b_lane = (uint32_t)((nw * 32 + ((lid >> 4) & 1) * 8 + (lid & 7)) * (BSTH * 2)
                                       + ((lid >> 3) & 1) * 16);

    const int bs_n  = tid >> 1;
    const int bs_kb = (tid & 1) * 2;
    const uint32_t bs_dst = bbase + (uint32_t)(bs_n * (BSTH * 2) + bs_kb * 16);

    for (int nt = 0; nt < 9; ++nt) {
        const int n0 = nt * 128;
        float c[4][4][4];
        #pragma unroll
        for (int i = 0; i < 4; ++i)
            #pragma unroll
            for (int j = 0; j < 4; ++j)
                c[i][j][0] = c[i][j][1] = c[i][j][2] = c[i][j][3] = 0.f;

        for (int s = 0; s < 12; ++s) {
            __syncthreads();            // prior-stage readers done
            {
                const uint32_t* src = g_wh + (size_t)(n0 + bs_n) * 192
                                      + s * 16 + bs_kb * 4;
                CP_ASYNC16(bs_dst,      (const void*)src);
                CP_ASYNC16(bs_dst + 16, (const void*)(src + 4));
                CP_COMMIT();
                CP_WAIT0();
            }
            __syncthreads();

            #pragma unroll
            for (int kc = 0; kc < 2; ++kc) {
                uint32_t a[4][4], bb[2][4];
                const uint32_t a_base = abase + a_lane
                    + (uint32_t)((s * 32 + kc * 16) * (ASTH * 2));
                #pragma unroll
                for (int i = 0; i < 4; ++i)
                    ldsm_x4_t(a[i][0], a[i][1], a[i][2], a[i][3],
                              a_base + (uint32_t)(i * 32));
                const uint32_t b_base = bbase + b_lane + (uint32_t)(kc * 32);
                #pragma unroll
                for (int jp = 0; jp < 2; ++jp)
                    ldsm_x4(bb[jp][0], bb[jp][1], bb[jp][2], bb[jp][3],
                            b_base + (uint32_t)(jp * 16 * (BSTH * 2)));
                #pragma unroll
                for (int i = 0; i < 4; ++i)
                    #pragma unroll
                    for (int j = 0; j < 4; ++j) {
                        const int jp = j >> 1, lo = (j & 1) * 2;
                        mma_f16(c[i][j][0], c[i][j][1], c[i][j][2], c[i][j][3],
                                a[i][0], a[i][1], a[i][2], a[i][3],
                                bb[jp][lo], bb[jp][lo + 1]);
                    }
            }
        }

        // ---- Epilogue: bias + q-scale, pack fp16, quad transpose, STG.128 ----
        const float qsc = (n0 < 384) ? 0.10206207261596577f : 1.0f;
        float2 bv[4];
        #pragma unroll
        for (int j = 0; j < 4; ++j)
            bv[j] = *(const float2*)(bias + n0 + nw * 32 + j * 8 + lr * 2);

        const int gcol = (n0 + nw * 32 + lr * 8) >> 1;
        #pragma unroll
        for (int i = 0; i < 4; ++i) {
            uint32_t v0[4], v1[4];
            #pragma unroll
            for (int j = 0; j < 4; ++j) {
                v0[j] = pack_h2((c[i][j][0] + bv[j].x) * qsc,
                                (c[i][j][1] + bv[j].y) * qsc);
                v1[j] = pack_h2((c[i][j][2] + bv[j].x) * qsc,
                                (c[i][j][3] + bv[j].y) * qsc);
            }
            #pragma unroll
            for (int m = 1; m < 4; ++m) {
                v0[lr ^ m] = __shfl_xor_sync(0xffffffffu, v0[lr ^ m], m);
                v1[lr ^ m] = __shfl_xor_sync(0xffffffffu, v1[lr ^ m], m);
            }
            const int gm0 = m0 + mw * 64 + i * 16 + lq;
            *(uint4*)(g_qkvh + (size_t)gm0 * 576 + gcol) =
                make_uint4(v0[0], v0[1], v0[2], v0[3]);
            *(uint4*)(g_qkvh + (size_t)(gm0 + 8) * 576 + gcol) =
                make_uint4(v1[0], v1[1], v1[2], v1[3]);
        }
    }
}

// ---------------------------------------------------------------------------
// Kernel 2: tensor-core windowed attention — 2 heads per block.
//   256 threads = 2 warpgroups; warpgroup = one head (R10 compute verbatim).
//   Gmem reads become 384B-contiguous runs; 16384 blocks; 2 blocks/SM.
// ---------------------------------------------------------------------------
#define ROWB 208                      // bytes per Q/K/V row (104 halves)
#define MATB (64 * ROWB)              // 13312 bytes per matrix
#define HSET (3 * MATB)               // 39936 per head
#define OST  200                      // osm row stride (floats)
#define AT_SMEM (2 * HSET)            // 79872

__global__ void __launch_bounds__(256) attn_tc(float* __restrict__ out)
{
    extern __shared__ char smem[];
    const int tid  = threadIdx.x;
    const int wgid = tid >> 7;        // head within pair
    const int wrp  = (tid >> 5) & 3;
    const int lid  = tid & 31;
    const int lam  = lid & 3;
    const int win  = blockIdx.x;
    const int hp   = blockIdx.y;      // head pair (0: heads 0,1; 1: heads 2,3)
    const int b    = win >> 10;
    const int wh   = (win >> 5) & 31;
    const int ww   = win & 31;

    const uint32_t sbase = smem_u32(smem);
    const uint32_t qb = sbase + (uint32_t)(wgid * HSET);
    const uint32_t kb = qb + MATB;
    const uint32_t vb = kb + MATB;
    uint32_t* smw = (uint32_t*)smem;
    float* osm = (float*)smem;        // reused AFTER AV (post-sync)

    // Kick off all Q/K/V loads first: 49 tok x 72 chunks (2 heads x 3 segs x 12)
    // Chunk order = ascending gmem word -> 384B contiguous runs per (tok,seg).
    #pragma unroll
    for (int p = 0; p < 14; ++p) {
        int e = p * 256 + tid;
        if (e < 3528) {
            int tok = e / 72, c = e % 72;
            int seg = c / 24, hl = (c % 24) / 12, f4 = c % 12;
            const uint32_t* src = g_qkvh
                + ((size_t)b * HWB + (wh * 7 + tok / 7) * W_IMG + ww * 7 + tok % 7) * 576
                + seg * 192 + (hp * 2 + hl) * 48 + f4 * 4;
            uint32_t dst = sbase + (uint32_t)(hl * HSET + seg * MATB
                                              + tok * ROWB + f4 * 16);
            CP_ASYNC16(dst, (const void*)src);
        }
    }
    CP_COMMIT();

    // Zero pad rows 49..63 of both heads' Q/K/V while loads fly (52 words/row)
    for (int i = tid; i < 4680; i += 256) {
        int hl = i / 2340, rem = i % 2340;
        int arr = rem / 780, r2 = rem % 780;
        smw[hl * (HSET / 4) + arr * 3328 + (49 + r2 / 52) * 52 + (r2 % 52)] = 0u;
    }
    CP_WAIT0();
    __syncthreads();

    // ---- Scores: S[q][key] = Q . K (per warpgroup = per head) ----
    const int q0 = wrp * 16;
    const uint32_t a_addr = qb + (uint32_t)((q0 + (lid & 15)) * ROWB + (lid >> 4) * 16);
    const uint32_t k_rsel = (uint32_t)((((lid >> 4) & 1) * 8 + (lid & 7)) * ROWB
                                       + ((lid >> 3) & 1) * 16);
    float sc[7][4];
    #pragma unroll
    for (int t = 0; t < 7; ++t)
        sc[t][0] = sc[t][1] = sc[t][2] = sc[t][3] = 0.f;

    #pragma unroll
    for (int s = 0; s < 6; ++s) {
        uint32_t a0, a1, a2, a3;
        ldsm_x4(a0, a1, a2, a3, a_addr + (uint32_t)(s * 32));
        #pragma unroll
        for (int np = 0; np < 4; ++np) {
            uint32_t r0, r1, r2, r3;
            ldsm_x4(r0, r1, r2, r3, kb + k_rsel + (uint32_t)(np * 16 * ROWB + s * 32));
            mma_f16(sc[2*np][0], sc[2*np][1], sc[2*np][2], sc[2*np][3],
                    a0, a1, a2, a3, r0, r1);
            if (np < 3)
                mma_f16(sc[2*np+1][0], sc[2*np+1][1], sc[2*np+1][2], sc[2*np+1][3],
                        a0, a1, a2, a3, r2, r3);
        }
    }

    // ---- Softmax in registers ----
    float mx0 = -1e30f, mx1 = -1e30f;
    #pragma unroll
    for (int t = 0; t < 6; ++t) {
        mx0 = fmaxf(mx0, fmaxf(sc[t][0], sc[t][1]));
        mx1 = fmaxf(mx1, fmaxf(sc[t][2], sc[t][3]));
    }
    if (lam == 0) { mx0 = fmaxf(mx0, sc[6][0]); mx1 = fmaxf(mx1, sc[6][2]); }
    mx0 = fmaxf(mx0, __shfl_xor_sync(0xffffffffu, mx0, 1));
    mx0 = fmaxf(mx0, __shfl_xor_sync(0xffffffffu, mx0, 2));
    mx1 = fmaxf(mx1, __shfl_xor_sync(0xffffffffu, mx1, 1));
    mx1 = fmaxf(mx1, __shfl_xor_sync(0xffffffffu, mx1, 2));

    float pr[7][4];
    float sum0 = 0.f, sum1 = 0.f;
    #pragma unroll
    for (int t = 0; t < 6; ++t) {
        pr[t][0] = __expf(sc[t][0] - mx0);
        pr[t][1] = __expf(sc[t][1] - mx0);
        pr[t][2] = __expf(sc[t][2] - mx1);
        pr[t][3] = __expf(sc[t][3] - mx1);
        sum0 += pr[t][0] + pr[t][1];
        sum1 += pr[t][2] + pr[t][3];
    }
    pr[6][0] = (lam == 0) ? __expf(sc[6][0] - mx0) : 0.f;
    pr[6][1] = 0.f;
    pr[6][2] = (lam == 0) ? __expf(sc[6][2] - mx1) : 0.f;
    pr[6][3] = 0.f;
    sum0 += pr[6][0];
    sum1 += pr[6][2];
    sum0 += __shfl_xor_sync(0xffffffffu, sum0, 1);
    sum0 += __shfl_xor_sync(0xffffffffu, sum0, 2);
    sum1 += __shfl_xor_sync(0xffffffffu, sum1, 1);
    sum1 += __shfl_xor_sync(0xffffffffu, sum1, 2);
    const float inv0 = 1.f / sum0;
    const float inv1 = 1.f / sum1;

    // ---- AV: out = P . V ----
    float co[12][4];
    #pragma unroll
    for (int t = 0; t < 12; ++t)
        co[t][0] = co[t][1] = co[t][2] = co[t][3] = 0.f;

    const uint32_t v_rsel = (uint32_t)((lid & 15) * ROWB + ((lid >> 4) & 1) * 16);
    #pragma unroll
    for (int t = 0; t < 4; ++t) {
        uint32_t a0 = pack_h2(pr[2*t][0], pr[2*t][1]);
        uint32_t a1 = pack_h2(pr[2*t][2], pr[2*t][3]);
        uint32_t a2 = 0u, a3 = 0u;
        if (t < 3) {
            a2 = pack_h2(pr[2*t+1][0], pr[2*t+1][1]);
            a3 = pack_h2(pr[2*t+1][2], pr[2*t+1][3]);
        }
        #pragma unroll
        for (int np = 0; np < 6; ++np) {
            uint32_t r0, r1, r2, r3;
            ldsm_x4_t(r0, r1, r2, r3, vb + v_rsel + (uint32_t)(t * 16 * ROWB + np * 32));
            mma_f16(co[2*np][0], co[2*np][1], co[2*np][2], co[2*np][3],
                    a0, a1, a2, a3, r0, r1);
            mma_f16(co[2*np+1][0], co[2*np+1][1], co[2*np+1][2], co[2*np+1][3],
                    a0, a1, a2, a3, r2, r3);
        }
    }
    __syncthreads();   // both heads done with Q/K/V smem -> reuse as osm

    // ---- Stage normalized output rows to osm[49][2*96] (stride 200) ----
    {
        const int r   = lid >> 2;
        const int rg0 = q0 + r;
        const int rg8 = q0 + r + 8;
        const int dh  = wgid * 96;
        #pragma unroll
        for (int nt = 0; nt < 12; ++nt) {
            const int d = dh + nt * 8 + 2 * lam;
            if (rg0 < 49)
                *(float2*)(osm + rg0 * OST + d) =
                    make_float2(co[nt][0] * inv0, co[nt][1] * inv0);
            if (rg8 < 49)
                *(float2*)(osm + rg8 * OST + d) =
                    make_float2(co[nt][2] * inv1, co[nt][3] * inv1);
        }
    }
    __syncthreads();

    // ---- Coalesced-ish global write (w-contiguous runs of 7) ----
    for (int e = tid; e < 9408; e += 256) {
        int tok = e % 49, d = e / 49;                 // d in 0..191
        out[(((size_t)b * C_DIM + hp * 192 + d) * H_IMG + wh * 7 + tok / 7) * W_IMG
            + ww * 7 + tok % 7] = osm[tok * OST + (d >= 96 ? 96 + (d - 96) : d)];
    }
}

// ---------------------------------------------------------------------------
extern "C" void kernel_launch(void* const* d_in, const int* in_sizes, int n_in,
                              void* d_out, int out_size)
{
    const float* x    = (const float*)d_in[0];
    const float* w    = (const float*)d_in[1];
    const float* bias = (const float*)d_in[2];
    float* out        = (float*)d_out;

    cudaFuncSetAttribute(qkv_mma, cudaFuncAttributeMaxDynamicSharedMemorySize,
                         (int)QKV_SMEM);
    cudaFuncSetAttribute(attn_tc, cudaFuncAttributeMaxDynamicSharedMemorySize,
                         (int)AT_SMEM);

    wconv<<<432, 256>>>(w);
    qkv_mma<<<M_TOT / 128, 256, QKV_SMEM>>>(x, bias);
    attn_tc<<<dim3(B_SZ * 32 * 32, 2), 256, AT_SMEM>>>(out);
}

// round 13
// speedup vs baseline: 1.1881x; 1.0076x over previous
#include <cuda_runtime.h>
#include <cstdint>

// Problem constants
#define C_DIM   384
#define N_DIM   1152
#define B_SZ    8
#define H_IMG   224
#define W_IMG   224
#define HWB     50176
#define M_TOT   401408
#define HD      96
#define NHEADS  4

// QKV scratch in fp16 (half2 words): [M_TOT][576 words]; q pre-scaled by 96^-0.5
__device__ uint32_t g_qkvh[(size_t)M_TOT * 576];
// Pre-converted W in fp16 (half2 words): [1152][384] halves
__device__ uint32_t g_wh[221184];

__device__ __forceinline__ uint32_t pack_h2(float lo, float hi) {
    uint32_t r;
    asm("cvt.rn.f16x2.f32 %0, %1, %2;" : "=r"(r) : "f"(hi), "f"(lo));
    return r;   // d<15:0> = lo, d<31:16> = hi
}

__device__ __forceinline__ uint32_t smem_u32(const void* p) {
    uint32_t a;
    asm("{ .reg .u64 t; cvta.to.shared.u64 t, %1; cvt.u32.u64 %0, t; }"
        : "=r"(a) : "l"(p));
    return a;
}

#define CP_ASYNC16(dst, src) \
    asm volatile("cp.async.cg.shared.global [%0], [%1], 16;" \
                 :: "r"(dst), "l"(src) : "memory")
#define CP_COMMIT()  asm volatile("cp.async.commit_group;" ::: "memory")
#define CP_WAIT0()   asm volatile("cp.async.wait_group 0;" ::: "memory")

__device__ __forceinline__ void ldsm_x4(uint32_t& r0, uint32_t& r1,
                                        uint32_t& r2, uint32_t& r3, uint32_t a) {
    asm volatile("ldmatrix.sync.aligned.m8n8.x4.shared.b16 {%0,%1,%2,%3}, [%4];"
                 : "=r"(r0), "=r"(r1), "=r"(r2), "=r"(r3) : "r"(a));
}
__device__ __forceinline__ void ldsm_x4_t(uint32_t& r0, uint32_t& r1,
                                          uint32_t& r2, uint32_t& r3, uint32_t a) {
    asm volatile("ldmatrix.sync.aligned.m8n8.x4.trans.shared.b16 {%0,%1,%2,%3}, [%4];"
                 : "=r"(r0), "=r"(r1), "=r"(r2), "=r"(r3) : "r"(a));
}

__device__ __forceinline__ void mma_f16(float& c0, float& c1, float& c2, float& c3,
                                        uint32_t a0, uint32_t a1, uint32_t a2, uint32_t a3,
                                        uint32_t b0, uint32_t b1) {
    asm volatile(
        "mma.sync.aligned.m16n8k16.row.col.f32.f16.f16.f32 "
        "{%0,%1,%2,%3}, {%4,%5,%6,%7}, {%8,%9}, {%0,%1,%2,%3};"
        : "+f"(c0), "+f"(c1), "+f"(c2), "+f"(c3)
        : "r"(a0), "r"(a1), "r"(a2), "r"(a3), "r"(b0), "r"(b1));
}

// ---------------------------------------------------------------------------
// Kernel 0: one-time W fp32 -> fp16 conversion
// ---------------------------------------------------------------------------
__global__ void __launch_bounds__(256) wconv(const float* __restrict__ w)
{
    int i = blockIdx.x * 256 + threadIdx.x;
    if (i < 110592) {
        float4 v = ((const float4*)w)[i];
        uint2 o;
        o.x = pack_h2(v.x, v.y);
        o.y = pack_h2(v.z, v.w);
        ((uint2*)g_wh)[i] = o;
    }
}

// ---------------------------------------------------------------------------
// Kernel 1: QKV GEMM — 32k stages, double-buffered prefetch-ahead cp.async.
//   A[k][m] fp16, 256B rows, XOR swizzle: phys_chunk = (c&8)|((c&7)^(k&7)).
//   B[n][k] fp16, 64B rows, XOR swizzle: phys_chunk = (c ^ ((n>>1)&3))&3.
//   12 stages (32 k-halves) per N-tile; prefetch s+1 while computing s;
//   one __syncthreads per stage, wait lands after ~512 cyc of MMA.
// ---------------------------------------------------------------------------
#define AS_BYTES 98304                      // 384 * 256
#define BSTG     8192                       // 128 rows * 64B
#define QKV_SMEM (AS_BYTES + 2 * BSTG)      // 114,688 -> 2 CTAs/SM

__global__ void __launch_bounds__(256, 2) qkv_mma(
    const float* __restrict__ x,
    const float* __restrict__ bias)
{
    extern __shared__ char smem[];
    const uint32_t abase = smem_u32(smem);
    const uint32_t bbase = abase + AS_BYTES;

    const int tid = threadIdx.x;
    const int wid = tid >> 5;
    const int lid = tid & 31;
    const int mw  = wid & 1;
    const int nw  = wid >> 1;
    const int lq  = lid >> 2;
    const int lr  = lid & 3;
    const int bit3 = (lid >> 3) & 1;
    const int bit4 = (lid >> 4) & 1;

    const int m0 = blockIdx.x * 128;
    const int b  = m0 / HWB;
    const float* xb = x + (size_t)b * C_DIM * HWB + (m0 - b * HWB);

    // B-stage cp.async mapping: thread -> (row = tid>>1, 2 logical chunks)
    const int bs_row = tid >> 1;
    const int bs_c0  = (tid & 1) * 2;
    const uint32_t phys0 = (uint32_t)(((bs_c0 ^ ((bs_row >> 1) & 3)) & 3) * 16);
    const uint32_t bs_d0 = bbase + (uint32_t)(bs_row * 64) + phys0;
    const uint32_t bs_d1 = bs_d0 ^ 16u;     // chunk c0+1 flips phys bit0
    const uint32_t* bs_srcb = g_wh + (size_t)bs_row * 192 + bs_c0 * 4;

    // ---- Preload stage (nt=0, s=0) into buf 0 ----
    CP_ASYNC16(bs_d0, (const void*)bs_srcb);
    CP_ASYNC16(bs_d1, (const void*)(bs_srcb + 4));
    CP_COMMIT();

    // ---- A prologue: As[k][m] fp16, XOR-swizzled chunks (R11-verified) ----
    for (int i = tid; i < 12288; i += 256) {
        int k = i >> 5, m4 = i & 31;
        float4 v = *(const float4*)(xb + (size_t)k * HWB + m4 * 4);
        uint32_t h0 = pack_h2(v.x, v.y);
        uint32_t h1 = pack_h2(v.z, v.w);
        int cl = m4 >> 1;
        uint32_t off = (uint32_t)(k * 256
            + (((cl & 8) | ((cl & 7) ^ (k & 7))) * 16) + (m4 & 1) * 8);
        asm volatile("st.shared.v2.b32 [%0], {%1,%2};"
                     :: "r"(abase + off), "r"(h0), "r"(h1));
    }
    CP_WAIT0();
    __syncthreads();

    // Per-lane ldmatrix address components
    const uint32_t a_row = (uint32_t)((((lid & 7) + bit4 * 8) * 256) + mw * 128);
    uint32_t coff[4];
    #pragma unroll
    for (int i = 0; i < 4; ++i)
        coff[i] = (uint32_t)((((bit3 + 2 * i) ^ (lid & 7)) & 7) * 16);

    const int  b_row   = nw * 32 + bit4 * 8 + (lid & 7);
    const uint32_t b_roff = (uint32_t)(b_row * 64);
    const uint32_t swzn   = (uint32_t)((b_row >> 1) & 3);
    uint32_t bpc[2];
    bpc[0] = (uint32_t)((((0u + bit3) ^ swzn) & 3u) * 16u);
    bpc[1] = (uint32_t)((((2u + bit3) ^ swzn) & 3u) * 16u);

    for (int nt = 0; nt < 9; ++nt) {
        const int n0 = nt * 128;
        float c[4][4][4];
        #pragma unroll
        for (int i = 0; i < 4; ++i)
            #pragma unroll
            for (int j = 0; j < 4; ++j)
                c[i][j][0] = c[i][j][1] = c[i][j][2] = c[i][j][3] = 0.f;

        for (int s = 0; s < 12; ++s) {
            const int g = nt * 12 + s;           // global stage id (parity = s&1)
            const bool pf = (g < 107);

            // ---- Prefetch stage g+1 into the other buffer ----
            if (pf) {
                const int gn  = g + 1;
                const int pn0 = (gn / 12) * 128;
                const int ps  = gn - (gn / 12) * 12;
                const uint32_t dbuf = (uint32_t)((gn & 1) * BSTG);
                const uint32_t* src = bs_srcb + (size_t)pn0 * 192 + ps * 16;
                CP_ASYNC16(bs_d0 + dbuf, (const void*)src);
                CP_ASYNC16(bs_d1 + dbuf, (const void*)(src + 4));
                CP_COMMIT();
            }

            // ---- Compute stage s from buf (g & 1) ----
            const uint32_t bufb = bbase + (uint32_t)((g & 1) * BSTG);
            #pragma unroll
            for (int kc = 0; kc < 2; ++kc) {
                uint32_t a[4][4], bb[2][4];
                const uint32_t sA = abase + (uint32_t)(s * 8192 + kc * 4096) + a_row;
                #pragma unroll
                for (int i = 0; i < 4; ++i)
                    ldsm_x4_t(a[i][0], a[i][1], a[i][2], a[i][3], sA + coff[i]);
                const uint32_t sB = bufb + b_roff + bpc[kc];
                #pragma unroll
                for (int jp = 0; jp < 2; ++jp)
                    ldsm_x4(bb[jp][0], bb[jp][1], bb[jp][2], bb[jp][3],
                            sB + (uint32_t)(jp * 1024));
                #pragma unroll
                for (int i = 0; i < 4; ++i)
                    #pragma unroll
                    for (int j = 0; j < 4; ++j) {
                        const int jp = j >> 1, lo = (j & 1) * 2;
                        mma_f16(c[i][j][0], c[i][j][1], c[i][j][2], c[i][j][3],
                                a[i][0], a[i][1], a[i][2], a[i][3],
                                bb[jp][lo], bb[jp][lo + 1]);
                    }
            }

            if (pf) CP_WAIT0();
            __syncthreads();
        }

        // ---- Epilogue: bias + q-scale, pack fp16, quad transpose, STG.128 ----
        const float qsc = (n0 < 384) ? 0.10206207261596577f : 1.0f;
        float2 bv[4];
        #pragma unroll
        for (int j = 0; j < 4; ++j)
            bv[j] = *(const float2*)(bias + n0 + nw * 32 + j * 8 + lr * 2);

        const int gcol = (n0 + nw * 32 + lr * 8) >> 1;
        #pragma unroll
        for (int i = 0; i < 4; ++i) {
            uint32_t v0[4], v1[4];
            #pragma unroll
            for (int j = 0; j < 4; ++j) {
                v0[j] = pack_h2((c[i][j][0] + bv[j].x) * qsc,
                                (c[i][j][1] + bv[j].y) * qsc);
                v1[j] = pack_h2((c[i][j][2] + bv[j].x) * qsc,
                                (c[i][j][3] + bv[j].y) * qsc);
            }
            #pragma unroll
            for (int m = 1; m < 4; ++m) {
                v0[lr ^ m] = __shfl_xor_sync(0xffffffffu, v0[lr ^ m], m);
                v1[lr ^ m] = __shfl_xor_sync(0xffffffffu, v1[lr ^ m], m);
            }
            const int gm0 = m0 + mw * 64 + i * 16 + lq;
            *(uint4*)(g_qkvh + (size_t)gm0 * 576 + gcol) =
                make_uint4(v0[0], v0[1], v0[2], v0[3]);
            *(uint4*)(g_qkvh + (size_t)(gm0 + 8) * 576 + gcol) =
                make_uint4(v1[0], v1[1], v1[2], v1[3]);
        }
    }
}

// ---------------------------------------------------------------------------
// Kernel 2: tensor-core windowed attention — 2 heads per block (R12 verbatim)
// ---------------------------------------------------------------------------
#define ROWB 208                      // bytes per Q/K/V row (104 halves)
#define MATB (64 * ROWB)              // 13312 bytes per matrix
#define HSET (3 * MATB)               // 39936 per head
#define OST  200                      // osm row stride (floats)
#define AT_SMEM (2 * HSET)            // 79872

__global__ void __launch_bounds__(256) attn_tc(float* __restrict__ out)
{
    extern __shared__ char smem[];
    const int tid  = threadIdx.x;
    const int wgid = tid >> 7;        // head within pair
    const int wrp  = (tid >> 5) & 3;
    const int lid  = tid & 31;
    const int lam  = lid & 3;
    const int win  = blockIdx.x;
    const int hp   = blockIdx.y;      // head pair
    const int b    = win >> 10;
    const int wh   = (win >> 5) & 31;
    const int ww   = win & 31;

    const uint32_t sbase = smem_u32(smem);
    const uint32_t qb = sbase + (uint32_t)(wgid * HSET);
    const uint32_t kb = qb + MATB;
    const uint32_t vb = kb + MATB;
    uint32_t* smw = (uint32_t*)smem;
    float* osm = (float*)smem;        // reused AFTER AV (post-sync)

    // Kick off all Q/K/V loads first: 49 tok x 72 chunks (2 heads x 3 segs x 12)
    #pragma unroll
    for (int p = 0; p < 14; ++p) {
        int e = p * 256 + tid;
        if (e < 3528) {
            int tok = e / 72, c = e % 72;
            int seg = c / 24, hl = (c % 24) / 12, f4 = c % 12;
            const uint32_t* src = g_qkvh
                + ((size_t)b * HWB + (wh * 7 + tok / 7) * W_IMG + ww * 7 + tok % 7) * 576
                + seg * 192 + (hp * 2 + hl) * 48 + f4 * 4;
            uint32_t dst = sbase + (uint32_t)(hl * HSET + seg * MATB
                                              + tok * ROWB + f4 * 16);
            CP_ASYNC16(dst, (const void*)src);
        }
    }
    CP_COMMIT();

    // Zero pad rows 49..63 of both heads' Q/K/V while loads fly
    for (int i = tid; i < 4680; i += 256) {
        int hl = i / 2340, rem = i % 2340;
        int arr = rem / 780, r2 = rem % 780;
        smw[hl * (HSET / 4) + arr * 3328 + (49 + r2 / 52) * 52 + (r2 % 52)] = 0u;
    }
    CP_WAIT0();
    __syncthreads();

    // ---- Scores: S[q][key] = Q . K (per warpgroup = per head) ----
    const int q0 = wrp * 16;
    const uint32_t a_addr = qb + (uint32_t)((q0 + (lid & 15)) * ROWB + (lid >> 4) * 16);
    const uint32_t k_rsel = (uint32_t)((((lid >> 4) & 1) * 8 + (lid & 7)) * ROWB
                                       + ((lid >> 3) & 1) * 16);
    float sc[7][4];
    #pragma unroll
    for (int t = 0; t < 7; ++t)
        sc[t][0] = sc[t][1] = sc[t][2] = sc[t][3] = 0.f;

    #pragma unroll
    for (int s = 0; s < 6; ++s) {
        uint32_t a0, a1, a2, a3;
        ldsm_x4(a0, a1, a2, a3, a_addr + (uint32_t)(s * 32));
        #pragma unroll
        for (int np = 0; np < 4; ++np) {
            uint32_t r0, r1, r2, r3;
            ldsm_x4(r0, r1, r2, r3, kb + k_rsel + (uint32_t)(np * 16 * ROWB + s * 32));
            mma_f16(sc[2*np][0], sc[2*np][1], sc[2*np][2], sc[2*np][3],
                    a0, a1, a2, a3, r0, r1);
            if (np < 3)
                mma_f16(sc[2*np+1][0], sc[2*np+1][1], sc[2*np+1][2], sc[2*np+1][3],
                        a0, a1, a2, a3, r2, r3);
        }
    }

    // ---- Softmax in registers ----
    float mx0 = -1e30f, mx1 = -1e30f;
    #pragma unroll
    for (int t = 0; t < 6; ++t) {
        mx0 = fmaxf(mx0, fmaxf(sc[t][0], sc[t][1]));
        mx1 = fmaxf(mx1, fmaxf(sc[t][2], sc[t][3]));
    }
    if (lam == 0) { mx0 = fmaxf(mx0, sc[6][0]); mx1 = fmaxf(mx1, sc[6][2]); }
    mx0 = fmaxf(mx0, __shfl_xor_sync(0xffffffffu, mx0, 1));
    mx0 = fmaxf(mx0, __shfl_xor_sync(0xffffffffu, mx0, 2));
    mx1 = fmaxf(mx1, __shfl_xor_sync(0xffffffffu, mx1, 1));
    mx1 = fmaxf(mx1, __shfl_xor_sync(0xffffffffu, mx1, 2));

    float pr[7][4];
    float sum0 = 0.f, sum1 = 0.f;
    #pragma unroll
    for (int t = 0; t < 6; ++t) {
        pr[t][0] = __expf(sc[t][0] - mx0);
        pr[t][1] = __expf(sc[t][1] - mx0);
        pr[t][2] = __expf(sc[t][2] - mx1);
        pr[t][3] = __expf(sc[t][3] - mx1);
        sum0 += pr[t][0] + pr[t][1];
        sum1 += pr[t][2] + pr[t][3];
    }
    pr[6][0] = (lam == 0) ? __expf(sc[6][0] - mx0) : 0.f;
    pr[6][1] = 0.f;
    pr[6][2] = (lam == 0) ? __expf(sc[6][2] - mx1) : 0.f;
    pr[6][3] = 0.f;
    sum0 += pr[6][0];
    sum1 += pr[6][2];
    sum0 += __shfl_xor_sync(0xffffffffu, sum0, 1);
    sum0 += __shfl_xor_sync(0xffffffffu, sum0, 2);
    sum1 += __shfl_xor_sync(0xffffffffu, sum1, 1);
    sum1 += __shfl_xor_sync(0xffffffffu, sum1, 2);
    const float inv0 = 1.f / sum0;
    const float inv1 = 1.f / sum1;

    // ---- AV: out = P . V ----
    float co[12][4];
    #pragma unroll
    for (int t = 0; t < 12; ++t)
        co[t][0] = co[t][1] = co[t][2] = co[t][3] = 0.f;

    const uint32_t v_rsel = (uint32_t)((lid & 15) * ROWB + ((lid >> 4) & 1) * 16);
    #pragma unroll
    for (int t = 0; t < 4; ++t) {
        uint32_t a0 = pack_h2(pr[2*t][0], pr[2*t][1]);
        uint32_t a1 = pack_h2(pr[2*t][2], pr[2*t][3]);
        uint32_t a2 = 0u, a3 = 0u;
        if (t < 3) {
            a2 = pack_h2(pr[2*t+1][0], pr[2*t+1][1]);
            a3 = pack_h2(pr[2*t+1][2], pr[2*t+1][3]);
        }
        #pragma unroll
        for (int np = 0; np < 6; ++np) {
            uint32_t r0, r1, r2, r3;
            ldsm_x4_t(r0, r1, r2, r3, vb + v_rsel + (uint32_t)(t * 16 * ROWB + np * 32));
            mma_f16(co[2*np][0], co[2*np][1], co[2*np][2], co[2*np][3],
                    a0, a1, a2, a3, r0, r1);
            mma_f16(co[2*np+1][0], co[2*np+1][1], co[2*np+1][2], co[2*np+1][3],
                    a0, a1, a2, a3, r2, r3);
        }
    }
    __syncthreads();   // both heads done with Q/K/V smem -> reuse as osm

    // ---- Stage normalized output rows to osm[49][2*96] (stride 200) ----
    {
        const int r   = lid >> 2;
        const int rg0 = q0 + r;
        const int rg8 = q0 + r + 8;
        const int dh  = wgid * 96;
        #pragma unroll
        for (int nt = 0; nt < 12; ++nt) {
            const int d = dh + nt * 8 + 2 * lam;
            if (rg0 < 49)
                *(float2*)(osm + rg0 * OST + d) =
                    make_float2(co[nt][0] * inv0, co[nt][1] * inv0);
            if (rg8 < 49)
                *(float2*)(osm + rg8 * OST + d) =
                    make_float2(co[nt][2] * inv1, co[nt][3] * inv1);
        }
    }
    __syncthreads();

    // ---- Coalesced-ish global write (w-contiguous runs of 7) ----
    for (int e = tid; e < 9408; e += 256) {
        int tok = e % 49, d = e / 49;                 // d in 0..191
        out[(((size_t)b * C_DIM + hp * 192 + d) * H_IMG + wh * 7 + tok / 7) * W_IMG
            + ww * 7 + tok % 7] = osm[tok * OST + d];
    }
}

// ---------------------------------------------------------------------------
extern "C" void kernel_launch(void* const* d_in, const int* in_sizes, int n_in,
                              void* d_out, int out_size)
{
    const float* x    = (const float*)d_in[0];
    const float* w    = (const float*)d_in[1];
    const float* bias = (const float*)d_in[2];
    float* out        = (float*)d_out;

    cudaFuncSetAttribute(qkv_mma, cudaFuncAttributeMaxDynamicSharedMemorySize,
                         (int)QKV_SMEM);
    cudaFuncSetAttribute(attn_tc, cudaFuncAttributeMaxDynamicSharedMemorySize,
                         (int)AT_SMEM);

    wconv<<<432, 256>>>(w);
    qkv_mma<<<M_TOT / 128, 256, QKV_SMEM>>>(x, bias);
    attn_tc<<<dim3(B_SZ * 32 * 32, 2), 256, AT_SMEM>>>(out);
}

// round 14
// speedup vs baseline: 1.1995x; 1.0096x over previous
#include <cuda_runtime.h>
#include <cstdint>

// Problem constants
#define C_DIM   384
#define N_DIM   1152
#define B_SZ    8
#define H_IMG   224
#define W_IMG   224
#define HWB     50176
#define M_TOT   401408
#define HD      96
#define NHEADS  4

// QKV scratch in fp16 (half2 words): [M_TOT][576 words]; q pre-scaled by 96^-0.5
__device__ uint32_t g_qkvh[(size_t)M_TOT * 576];
// Pre-converted W in fp16 (half2 words): [1152][384] halves
__device__ uint32_t g_wh[221184];

__device__ __forceinline__ uint32_t pack_h2(float lo, float hi) {
    uint32_t r;
    asm("cvt.rn.f16x2.f32 %0, %1, %2;" : "=r"(r) : "f"(hi), "f"(lo));
    return r;   // d<15:0> = lo, d<31:16> = hi
}

__device__ __forceinline__ uint32_t smem_u32(const void* p) {
    uint32_t a;
    asm("{ .reg .u64 t; cvta.to.shared.u64 t, %1; cvt.u32.u64 %0, t; }"
        : "=r"(a) : "l"(p));
    return a;
}

#define CP_ASYNC16(dst, src) \
    asm volatile("cp.async.cg.shared.global [%0], [%1], 16;" \
                 :: "r"(dst), "l"(src) : "memory")
#define CP_COMMIT()  asm volatile("cp.async.commit_group;" ::: "memory")
#define CP_WAIT0()   asm volatile("cp.async.wait_group 0;" ::: "memory")

__device__ __forceinline__ void ldsm_x4(uint32_t& r0, uint32_t& r1,
                                        uint32_t& r2, uint32_t& r3, uint32_t a) {
    asm volatile("ldmatrix.sync.aligned.m8n8.x4.shared.b16 {%0,%1,%2,%3}, [%4];"
                 : "=r"(r0), "=r"(r1), "=r"(r2), "=r"(r3) : "r"(a));
}
__device__ __forceinline__ void ldsm_x4_t(uint32_t& r0, uint32_t& r1,
                                          uint32_t& r2, uint32_t& r3, uint32_t a) {
    asm volatile("ldmatrix.sync.aligned.m8n8.x4.trans.shared.b16 {%0,%1,%2,%3}, [%4];"
                 : "=r"(r0), "=r"(r1), "=r"(r2), "=r"(r3) : "r"(a));
}

__device__ __forceinline__ void mma_f16(float& c0, float& c1, float& c2, float& c3,
                                        uint32_t a0, uint32_t a1, uint32_t a2, uint32_t a3,
                                        uint32_t b0, uint32_t b1) {
    asm volatile(
        "mma.sync.aligned.m16n8k16.row.col.f32.f16.f16.f32 "
        "{%0,%1,%2,%3}, {%4,%5,%6,%7}, {%8,%9}, {%0,%1,%2,%3};"
        : "+f"(c0), "+f"(c1), "+f"(c2), "+f"(c3)
        : "r"(a0), "r"(a1), "r"(a2), "r"(a3), "r"(b0), "r"(b1));
}

// ---------------------------------------------------------------------------
// Kernel 0: one-time W fp32 -> fp16 conversion
// ---------------------------------------------------------------------------
__global__ void __launch_bounds__(256) wconv(const float* __restrict__ w)
{
    int i = blockIdx.x * 256 + threadIdx.x;
    if (i < 110592) {
        float4 v = ((const float4*)w)[i];
        uint2 o;
        o.x = pack_h2(v.x, v.y);
        o.y = pack_h2(v.z, v.w);
        ((uint2*)g_wh)[i] = o;
    }
}

// ---------------------------------------------------------------------------
// Kernel 1: QKV GEMM (R13 verbatim — at its HMMA-issue floor; do not touch)
// ---------------------------------------------------------------------------
#define AS_BYTES 98304                      // 384 * 256
#define BSTG     8192                       // 128 rows * 64B
#define QKV_SMEM (AS_BYTES + 2 * BSTG)      // 114,688 -> 2 CTAs/SM

__global__ void __launch_bounds__(256, 2) qkv_mma(
    const float* __restrict__ x,
    const float* __restrict__ bias)
{
    extern __shared__ char smem[];
    const uint32_t abase = smem_u32(smem);
    const uint32_t bbase = abase + AS_BYTES;

    const int tid = threadIdx.x;
    const int wid = tid >> 5;
    const int lid = tid & 31;
    const int mw  = wid & 1;
    const int nw  = wid >> 1;
    const int lq  = lid >> 2;
    const int lr  = lid & 3;
    const int bit3 = (lid >> 3) & 1;
    const int bit4 = (lid >> 4) & 1;

    const int m0 = blockIdx.x * 128;
    const int b  = m0 / HWB;
    const float* xb = x + (size_t)b * C_DIM * HWB + (m0 - b * HWB);

    const int bs_row = tid >> 1;
    const int bs_c0  = (tid & 1) * 2;
    const uint32_t phys0 = (uint32_t)(((bs_c0 ^ ((bs_row >> 1) & 3)) & 3) * 16);
    const uint32_t bs_d0 = bbase + (uint32_t)(bs_row * 64) + phys0;
    const uint32_t bs_d1 = bs_d0 ^ 16u;
    const uint32_t* bs_srcb = g_wh + (size_t)bs_row * 192 + bs_c0 * 4;

    CP_ASYNC16(bs_d0, (const void*)bs_srcb);
    CP_ASYNC16(bs_d1, (const void*)(bs_srcb + 4));
    CP_COMMIT();

    for (int i = tid; i < 12288; i += 256) {
        int k = i >> 5, m4 = i & 31;
        float4 v = *(const float4*)(xb + (size_t)k * HWB + m4 * 4);
        uint32_t h0 = pack_h2(v.x, v.y);
        uint32_t h1 = pack_h2(v.z, v.w);
        int cl = m4 >> 1;
        uint32_t off = (uint32_t)(k * 256
            + (((cl & 8) | ((cl & 7) ^ (k & 7))) * 16) + (m4 & 1) * 8);
        asm volatile("st.shared.v2.b32 [%0], {%1,%2};"
                     :: "r"(abase + off), "r"(h0), "r"(h1));
    }
    CP_WAIT0();
    __syncthreads();

    const uint32_t a_row = (uint32_t)((((lid & 7) + bit4 * 8) * 256) + mw * 128);
    uint32_t coff[4];
    #pragma unroll
    for (int i = 0; i < 4; ++i)
        coff[i] = (uint32_t)((((bit3 + 2 * i) ^ (lid & 7)) & 7) * 16);

    const int  b_row   = nw * 32 + bit4 * 8 + (lid & 7);
    const uint32_t b_roff = (uint32_t)(b_row * 64);
    const uint32_t swzn   = (uint32_t)((b_row >> 1) & 3);
    uint32_t bpc[2];
    bpc[0] = (uint32_t)((((0u + bit3) ^ swzn) & 3u) * 16u);
    bpc[1] = (uint32_t)((((2u + bit3) ^ swzn) & 3u) * 16u);

    for (int nt = 0; nt < 9; ++nt) {
        const int n0 = nt * 128;
        float c[4][4][4];
        #pragma unroll
        for (int i = 0; i < 4; ++i)
            #pragma unroll
            for (int j = 0; j < 4; ++j)
                c[i][j][0] = c[i][j][1] = c[i][j][2] = c[i][j][3] = 0.f;

        for (int s = 0; s < 12; ++s) {
            const int g = nt * 12 + s;
            const bool pf = (g < 107);

            if (pf) {
                const int gn  = g + 1;
                const int pn0 = (gn / 12) * 128;
                const int ps  = gn - (gn / 12) * 12;
                const uint32_t dbuf = (uint32_t)((gn & 1) * BSTG);
                const uint32_t* src = bs_srcb + (size_t)pn0 * 192 + ps * 16;
                CP_ASYNC16(bs_d0 + dbuf, (const void*)src);
                CP_ASYNC16(bs_d1 + dbuf, (const void*)(src + 4));
                CP_COMMIT();
            }

            const uint32_t bufb = bbase + (uint32_t)((g & 1) * BSTG);
            #pragma unroll
            for (int kc = 0; kc < 2; ++kc) {
                uint32_t a[4][4], bb[2][4];
                const uint32_t sA = abase + (uint32_t)(s * 8192 + kc * 4096) + a_row;
                #pragma unroll
                for (int i = 0; i < 4; ++i)
                    ldsm_x4_t(a[i][0], a[i][1], a[i][2], a[i][3], sA + coff[i]);
                const uint32_t sB = bufb + b_roff + bpc[kc];
                #pragma unroll
                for (int jp = 0; jp < 2; ++jp)
                    ldsm_x4(bb[jp][0], bb[jp][1], bb[jp][2], bb[jp][3],
                            sB + (uint32_t)(jp * 1024));
                #pragma unroll
                for (int i = 0; i < 4; ++i)
                    #pragma unroll
                    for (int j = 0; j < 4; ++j) {
                        const int jp = j >> 1, lo = (j & 1) * 2;
                        mma_f16(c[i][j][0], c[i][j][1], c[i][j][2], c[i][j][3],
                                a[i][0], a[i][1], a[i][2], a[i][3],
                                bb[jp][lo], bb[jp][lo + 1]);
                    }
            }

            if (pf) CP_WAIT0();
            __syncthreads();
        }

        const float qsc = (n0 < 384) ? 0.10206207261596577f : 1.0f;
        float2 bv[4];
        #pragma unroll
        for (int j = 0; j < 4; ++j)
            bv[j] = *(const float2*)(bias + n0 + nw * 32 + j * 8 + lr * 2);

        const int gcol = (n0 + nw * 32 + lr * 8) >> 1;
        #pragma unroll
        for (int i = 0; i < 4; ++i) {
            uint32_t v0[4], v1[4];
            #pragma unroll
            for (int j = 0; j < 4; ++j) {
                v0[j] = pack_h2((c[i][j][0] + bv[j].x) * qsc,
                                (c[i][j][1] + bv[j].y) * qsc);
                v1[j] = pack_h2((c[i][j][2] + bv[j].x) * qsc,
                                (c[i][j][3] + bv[j].y) * qsc);
            }
            #pragma unroll
            for (int m = 1; m < 4; ++m) {
                v0[lr ^ m] = __shfl_xor_sync(0xffffffffu, v0[lr ^ m], m);
                v1[lr ^ m] = __shfl_xor_sync(0xffffffffu, v1[lr ^ m], m);
            }
            const int gm0 = m0 + mw * 64 + i * 16 + lq;
            *(uint4*)(g_qkvh + (size_t)gm0 * 576 + gcol) =
                make_uint4(v0[0], v0[1], v0[2], v0[3]);
            *(uint4*)(g_qkvh + (size_t)(gm0 + 8) * 576 + gcol) =
                make_uint4(v1[0], v1[1], v1[2], v1[3]);
        }
    }
}

// ---------------------------------------------------------------------------
// Kernel 2: tensor-core windowed attention — 2 heads/block, 3 blocks/SM.
//   Per head: Q 64 rows, K 56 rows (score np=3 only uses r0/r1; its extra
//   ldsm rows land in V region — in-bounds, finite, discarded), V 64 rows.
//   SMEM 76,544 B; probs packed to fp16 right after softmax (reg pressure).
// ---------------------------------------------------------------------------
#define ROWB 208                      // bytes per Q/K/V row (104 halves)
#define QMB  13312                    // Q: 64 rows
#define KMB  11648                    // K: 56 rows
#define VMB  13312                    // V: 64 rows
#define HSET (QMB + KMB + VMB)        // 38272 per head
#define OST  200                      // osm row stride (floats)
#define AT_SMEM (2 * HSET)            // 76544

__global__ void __launch_bounds__(256, 3) attn_tc(float* __restrict__ out)
{
    extern __shared__ char smem[];
    const int tid  = threadIdx.x;
    const int wgid = tid >> 7;        // head within pair
    const int wrp  = (tid >> 5) & 3;
    const int lid  = tid & 31;
    const int lam  = lid & 3;
    const int win  = blockIdx.x;
    const int hp   = blockIdx.y;      // head pair
    const int b    = win >> 10;
    const int wh   = (win >> 5) & 31;
    const int ww   = win & 31;

    const uint32_t sbase = smem_u32(smem);
    const uint32_t qb = sbase + (uint32_t)(wgid * HSET);
    const uint32_t kb = qb + QMB;
    const uint32_t vb = kb + KMB;
    uint32_t* smw = (uint32_t*)smem;
    float* osm = (float*)smem;        // reused AFTER AV (post-sync)

    // Kick off all Q/K/V loads: 49 tok x 72 chunks (2 heads x 3 segs x 12)
    #pragma unroll
    for (int p = 0; p < 14; ++p) {
        int e = p * 256 + tid;
        if (e < 3528) {
            int tok = e / 72, c = e % 72;
            int seg = c / 24, hl = (c % 24) / 12, f4 = c % 12;
            const uint32_t* src = g_qkvh
                + ((size_t)b * HWB + (wh * 7 + tok / 7) * W_IMG + ww * 7 + tok % 7) * 576
                + seg * 192 + (hp * 2 + hl) * 48 + f4 * 4;
            uint32_t sgo = (seg == 0) ? 0u : ((seg == 1) ? (uint32_t)QMB
                                                         : (uint32_t)(QMB + KMB));
            uint32_t dst = sbase + (uint32_t)(hl * HSET) + sgo
                         + (uint32_t)(tok * ROWB + f4 * 16);
            CP_ASYNC16(dst, (const void*)src);
        }
    }
    CP_COMMIT();

    // Zero pad rows while loads fly: Q 49-63, K 49-55, V 49-63 (both heads)
    // 2 heads x 37 rows x 52 words = 3848
    for (int i = tid; i < 3848; i += 256) {
        int hl = i / 1924, rem = i % 1924;
        int r37 = rem / 52, w = rem % 52;
        int base, r;
        if (r37 < 15)      { base = 0;    r = 49 + r37; }        // Q
        else if (r37 < 22) { base = 3328; r = 49 + r37 - 15; }   // K (words)
        else               { base = 6240; r = 49 + r37 - 22; }   // V
        smw[hl * (HSET / 4) + base + r * 52 + w] = 0u;
    }
    CP_WAIT0();
    __syncthreads();

    // ---- Scores: S[q][key] = Q . K (per warpgroup = per head) ----
    const int q0 = wrp * 16;
    const uint32_t a_addr = qb + (uint32_t)((q0 + (lid & 15)) * ROWB + (lid >> 4) * 16);
    const uint32_t k_rsel = (uint32_t)((((lid >> 4) & 1) * 8 + (lid & 7)) * ROWB
                                       + ((lid >> 3) & 1) * 16);
    float sc[7][4];
    #pragma unroll
    for (int t = 0; t < 7; ++t)
        sc[t][0] = sc[t][1] = sc[t][2] = sc[t][3] = 0.f;

    #pragma unroll
    for (int s = 0; s < 6; ++s) {
        uint32_t a0, a1, a2, a3;
        ldsm_x4(a0, a1, a2, a3, a_addr + (uint32_t)(s * 32));
        #pragma unroll
        for (int np = 0; np < 4; ++np) {
            uint32_t r0, r1, r2, r3;
            ldsm_x4(r0, r1, r2, r3, kb + k_rsel + (uint32_t)(np * 16 * ROWB + s * 32));
            mma_f16(sc[2*np][0], sc[2*np][1], sc[2*np][2], sc[2*np][3],
                    a0, a1, a2, a3, r0, r1);
            if (np < 3)
                mma_f16(sc[2*np+1][0], sc[2*np+1][1], sc[2*np+1][2], sc[2*np+1][3],
                        a0, a1, a2, a3, r2, r3);
        }
    }

    // ---- Softmax in registers; pack probs to fp16 immediately ----
    float mx0 = -1e30f, mx1 = -1e30f;
    #pragma unroll
    for (int t = 0; t < 6; ++t) {
        mx0 = fmaxf(mx0, fmaxf(sc[t][0], sc[t][1]));
        mx1 = fmaxf(mx1, fmaxf(sc[t][2], sc[t][3]));
    }
    if (lam == 0) { mx0 = fmaxf(mx0, sc[6][0]); mx1 = fmaxf(mx1, sc[6][2]); }
    mx0 = fmaxf(mx0, __shfl_xor_sync(0xffffffffu, mx0, 1));
    mx0 = fmaxf(mx0, __shfl_xor_sync(0xffffffffu, mx0, 2));
    mx1 = fmaxf(mx1, __shfl_xor_sync(0xffffffffu, mx1, 1));
    mx1 = fmaxf(mx1, __shfl_xor_sync(0xffffffffu, mx1, 2));

    uint32_t ph[7][2];                 // packed unnormalized probs
    float sum0 = 0.f, sum1 = 0.f;
    #pragma unroll
    for (int t = 0; t < 6; ++t) {
        float e0 = __expf(sc[t][0] - mx0);
        float e1 = __expf(sc[t][1] - mx0);
        float e2 = __expf(sc[t][2] - mx1);
        float e3 = __expf(sc[t][3] - mx1);
        sum0 += e0 + e1;
        sum1 += e2 + e3;
        ph[t][0] = pack_h2(e0, e1);
        ph[t][1] = pack_h2(e2, e3);
    }
    {
        float e0 = (lam == 0) ? __expf(sc[6][0] - mx0) : 0.f;
        float e2 = (lam == 0) ? __expf(sc[6][2] - mx1) : 0.f;
        sum0 += e0;
        sum1 += e2;
        ph[6][0] = pack_h2(e0, 0.f);
        ph[6][1] = pack_h2(e2, 0.f);
    }
    sum0 += __shfl_xor_sync(0xffffffffu, sum0, 1);
    sum0 += __shfl_xor_sync(0xffffffffu, sum0, 2);
    sum1 += __shfl_xor_sync(0xffffffffu, sum1, 1);
    sum1 += __shfl_xor_sync(0xffffffffu, sum1, 2);
    const float inv0 = 1.f / sum0;
    const float inv1 = 1.f / sum1;

    // ---- AV: out = P . V (normalize after) ----
    float co[12][4];
    #pragma unroll
    for (int t = 0; t < 12; ++t)
        co[t][0] = co[t][1] = co[t][2] = co[t][3] = 0.f;

    const uint32_t v_rsel = (uint32_t)((lid & 15) * ROWB + ((lid >> 4) & 1) * 16);
    #pragma unroll
    for (int t = 0; t < 4; ++t) {
        uint32_t a0 = ph[2*t][0];
        uint32_t a1 = ph[2*t][1];
        uint32_t a2 = (t < 3) ? ph[2*t+1][0] : 0u;
        uint32_t a3 = (t < 3) ? ph[2*t+1][1] : 0u;
        #pragma unroll
        for (int np = 0; np < 6; ++np) {
            uint32_t r0, r1, r2, r3;
            ldsm_x4_t(r0, r1, r2, r3, vb + v_rsel + (uint32_t)(t * 16 * ROWB + np * 32));
            mma_f16(co[2*np][0], co[2*np][1], co[2*np][2], co[2*np][3],
                    a0, a1, a2, a3, r0, r1);
            mma_f16(co[2*np+1][0], co[2*np+1][1], co[2*np+1][2], co[2*np+1][3],
                    a0, a1, a2, a3, r2, r3);
        }
    }
    __syncthreads();   // both heads done with Q/K/V smem -> reuse as osm

    // ---- Stage normalized output rows to osm[49][2*96] (stride 200) ----
    {
        const int r   = lid >> 2;
        const int rg0 = q0 + r;
        const int rg8 = q0 + r + 8;
        const int dh  = wgid * 96;
        #pragma unroll
        for (int nt = 0; nt < 12; ++nt) {
            const int d = dh + nt * 8 + 2 * lam;
            if (rg0 < 49)
                *(float2*)(osm + rg0 * OST + d) =
                    make_float2(co[nt][0] * inv0, co[nt][1] * inv0);
            if (rg8 < 49)
                *(float2*)(osm + rg8 * OST + d) =
                    make_float2(co[nt][2] * inv1, co[nt][3] * inv1);
        }
    }
    __syncthreads();

    // ---- Coalesced-ish global write (w-contiguous runs of 7) ----
    for (int e = tid; e < 9408; e += 256) {
        int tok = e % 49, d = e / 49;                 // d in 0..191
        out[(((size_t)b * C_DIM + hp * 192 + d) * H_IMG + wh * 7 + tok / 7) * W_IMG
            + ww * 7 + tok % 7] = osm[tok * OST + d];
    }
}

// ---------------------------------------------------------------------------
extern "C" void kernel_launch(void* const* d_in, const int* in_sizes, int n_in,
                              void* d_out, int out_size)
{
    const float* x    = (const float*)d_in[0];
    const float* w    = (const float*)d_in[1];
    const float* bias = (const float*)d_in[2];
    float* out        = (float*)d_out;

    cudaFuncSetAttribute(qkv_mma, cudaFuncAttributeMaxDynamicSharedMemorySize,
                         (int)QKV_SMEM);
    cudaFuncSetAttribute(attn_tc, cudaFuncAttributeMaxDynamicSharedMemorySize,
                         (int)AT_SMEM);

    wconv<<<432, 256>>>(w);
    qkv_mma<<<M_TOT / 128, 256, QKV_SMEM>>>(x, bias);
    attn_tc<<<dim3(B_SZ * 32 * 32, 2), 256, AT_SMEM>>>(out);
}